// round 4
// baseline (speedup 1.0000x reference)
#include <cuda_runtime.h>
#include <cuda_bf16.h>
#include <mma.h>
#include <cstdint>

using namespace nvcuda;
typedef __nv_bfloat16 bf16;

#define NB   1024
#define NK   16
#define NG   2000
#define ND   4000
#define NH   256
#define NR   16384
#define NRT  32768
#define OUTW 4256

// ------------------------- scratch (static device globals) -------------------
__device__ bf16  g_nfb[(long)NRT * ND];   // log-features, bf16 (250MB)
__device__ float g_att[NRT];
__device__ float g_w[2 * NB * NK];
__device__ float g_wsum[2 * NB];
__device__ bf16  g_aggb[2][NB * ND];
__device__ bf16  g_diffb[NB * ND];
__device__ bf16  g_encb[NB * ND];
__device__ bf16  g_Wa1b[ND * NH];
__device__ bf16  g_W1b[ND * NH];
__device__ bf16  g_Wdb[ND * NH];
__device__ bf16  g_Wrb[ND * NH];
__device__ float g_h1[4][NB * NH];
__device__ int   g_rowidx[NRT];

// ------------------------- tiny helpers --------------------------------------
__device__ __forceinline__ void cp16(void* smem, const void* gmem) {
    unsigned int s = (unsigned int)__cvta_generic_to_shared(smem);
    asm volatile("cp.async.cg.shared.global [%0], [%1], 16;" :: "r"(s), "l"(gmem));
}

// ------------------------- fused prep ----------------------------------------
// blocks [0,128): rowidx; [128,2128): 4 weight f32->bf16; [2128,4128): enc copy+convert
__global__ __launch_bounds__(256) void k_prep(
    const int* __restrict__ ni, const int* __restrict__ ni2,
    const float* __restrict__ Wa1, const float* __restrict__ W1,
    const float* __restrict__ Wd, const float* __restrict__ Wr,
    const float* __restrict__ enc, float* __restrict__ out)
{
    int blk = blockIdx.x, t = threadIdx.x;
    if (blk < 128) {
        int r = blk * 256 + t;
        int g = r >> 14;
        g_rowidx[r] = (g ? ni2 : ni)[r & (NR - 1)];
    } else if (blk < 2128) {
        int w = (blk - 128) / 500;
        int e = ((blk - 128) % 500) * 2048 + t * 8;
        const float* src = (w == 0) ? Wa1 : (w == 1) ? W1 : (w == 2) ? Wd : Wr;
        bf16* dst = (w == 0) ? g_Wa1b : (w == 1) ? g_W1b : (w == 2) ? g_Wdb : g_Wrb;
        float4 a = *(const float4*)(src + e);
        float4 b = *(const float4*)(src + e + 4);
        bf16 o[8] = { __float2bfloat16(a.x), __float2bfloat16(a.y),
                      __float2bfloat16(a.z), __float2bfloat16(a.w),
                      __float2bfloat16(b.x), __float2bfloat16(b.y),
                      __float2bfloat16(b.z), __float2bfloat16(b.w) };
        *(int4*)(dst + e) = *(int4*)o;
    } else {
        int e = (blk - 2128) * 2048 + t * 8;
        int b = e / ND, col = e % ND;
        float4 a = *(const float4*)(enc + e);
        float4 c = *(const float4*)(enc + e + 4);
        *(float4*)(out + (long)b * OUTW + col)     = a;
        *(float4*)(out + (long)b * OUTW + col + 4) = c;
        bf16 o[8] = { __float2bfloat16(a.x), __float2bfloat16(a.y),
                      __float2bfloat16(a.z), __float2bfloat16(a.w),
                      __float2bfloat16(c.x), __float2bfloat16(c.y),
                      __float2bfloat16(c.z), __float2bfloat16(c.w) };
        *(int4*)(g_encb + e) = *(int4*)o;
    }
}

// ------------------------- fused gather+log+GEMM+logit ------------------------
// Per CTA: 128 gathered rows. A built on the fly (fp32 LDG -> log -> bf16 smem,
// also streamed to g_nfb). B = Wa1b via cp.async double-buffer. Epilogue computes
// att[r] = sum_n tanh(C[r,n]+ba1[n])*Wa2[n] + ba2 fully in-CTA (N=256 = full width).
#define GT_SB_STRIDE 264
#define GT_SB_ELEMS  (32 * GT_SB_STRIDE)
#define GT_SA_STRIDE 40
#define GT_SA_OFF    (2 * GT_SB_ELEMS)
#define GT_SW_OFF    66048                      // bytes: sF = 64*258*4
#define GT_SMEM      (GT_SW_OFF + 2048)

__global__ __launch_bounds__(256, 1) void k_gatt(
    const float* __restrict__ sp, const float* __restrict__ un,
    const float* __restrict__ ba1, const float* __restrict__ Wa2,
    const float* __restrict__ ba2)
{
    extern __shared__ char smem[];
    bf16*  sB = (bf16*)smem;                      // 2 stages, 33792B
    bf16*  sA = (bf16*)smem + GT_SA_OFF;          // 10240B
    float* sF = (float*)smem;                     // epilogue buffer (reuse)
    float* sW1 = (float*)(smem + GT_SW_OFF);      // ba1
    float* sW2 = sW1 + 256;                       // Wa2

    const int tid  = threadIdx.x;
    const int warp = tid >> 5;
    const int wr   = warp >> 2;                   // 0..1
    const int wc   = warp & 3;                    // 0..3
    const int r0   = blockIdx.x * 128;

    sW1[tid] = ba1[tid];
    sW2[tid] = Wa2[tid];

    const int arow = tid >> 1;                    // 0..127
    const int acol = (tid & 1) * 16;              // 0 or 16
    const long idx = g_rowidx[r0 + arow];
    const float* psp = sp + idx * NG;
    const float* pun = un + idx * NG;

    wmma::fragment<wmma::accumulator, 16, 16, 16, float> c[4][4];
#pragma unroll
    for (int i = 0; i < 4; i++)
#pragma unroll
        for (int j = 0; j < 4; j++) wmma::fill_fragment(c[i][j], 0.0f);

    float rg[16];
    auto ldgA = [&](int it) {
        int kk = it * 32 + acol;
#pragma unroll
        for (int q = 0; q < 4; q++) {
            int col = kk + q * 4;
            const float* src = (col < NG) ? (psp + col) : (pun + col - NG);
            float4 v = *(const float4*)src;
            rg[q * 4 + 0] = v.x; rg[q * 4 + 1] = v.y;
            rg[q * 4 + 2] = v.z; rg[q * 4 + 3] = v.w;
        }
    };
    auto stA = [&](int it) {
        bf16 o[16];
#pragma unroll
        for (int q = 0; q < 16; q++) o[q] = __float2bfloat16(__logf(0.01f + rg[q]));
        bf16* da = &sA[arow * GT_SA_STRIDE + acol];
#pragma unroll
        for (int q = 0; q < 4; q++) *(uint2*)(da + q * 4) = ((uint2*)o)[q];
        bf16* dn = g_nfb + (long)(r0 + arow) * ND + it * 32 + acol;
        *(int4*)dn       = ((int4*)o)[0];
        *(int4*)(dn + 8) = ((int4*)o)[1];
    };
    auto cpB = [&](int it, int s) {
        int kk = it * 32;
#pragma unroll
        for (int c0 = 0; c0 < 4; c0++) {
            int ch = tid + c0 * 256;
            int row = ch >> 5, q = ch & 31;
            cp16(sB + s * GT_SB_ELEMS + row * GT_SB_STRIDE + q * 8,
                 g_Wa1b + (long)(kk + row) * NH + q * 8);
        }
        asm volatile("cp.async.commit_group;");
    };

    cpB(0, 0);
    ldgA(0);
    const int NT = ND / 32;                       // 125
    for (int it = 0; it < NT; it++) {
        int s = it & 1;
        if (it + 1 < NT) cpB(it + 1, s ^ 1);
        stA(it);
        if (it + 1 < NT) asm volatile("cp.async.wait_group 1;");
        else             asm volatile("cp.async.wait_group 0;");
        __syncthreads();
        if (it + 1 < NT) ldgA(it + 1);            // hide LDG under MMAs
#pragma unroll
        for (int ks = 0; ks < 32; ks += 16) {
            wmma::fragment<wmma::matrix_a, 16, 16, 16, bf16, wmma::row_major> af[4];
            wmma::fragment<wmma::matrix_b, 16, 16, 16, bf16, wmma::row_major> bfr[4];
#pragma unroll
            for (int i = 0; i < 4; i++)
                wmma::load_matrix_sync(af[i], &sA[(wr * 64 + i * 16) * GT_SA_STRIDE + ks], GT_SA_STRIDE);
#pragma unroll
            for (int j = 0; j < 4; j++)
                wmma::load_matrix_sync(bfr[j], &sB[s * GT_SB_ELEMS + ks * GT_SB_STRIDE + wc * 64 + j * 16], GT_SB_STRIDE);
#pragma unroll
            for (int i = 0; i < 4; i++)
#pragma unroll
                for (int j = 0; j < 4; j++)
                    wmma::mma_sync(c[i][j], af[i], bfr[j], c[i][j]);
        }
        __syncthreads();
    }

    // ---- epilogue: tanh + Wa2 dot, 64 rows per chunk ----
    float ba2v = ba2[0];
#pragma unroll
    for (int chunk = 0; chunk < 2; chunk++) {
        if (wr == chunk) {
#pragma unroll
            for (int i = 0; i < 4; i++)
#pragma unroll
                for (int j = 0; j < 4; j++)
                    wmma::store_matrix_sync(&sF[(i * 16) * 258 + wc * 64 + j * 16],
                                            c[i][j], 258, wmma::mem_row_major);
        }
        __syncthreads();
        int row = tid >> 2, q = tid & 3;
        const float* rp = sF + row * 258 + q * 64;
        const float* w1p = sW1 + q * 64;
        const float* w2p = sW2 + q * 64;
        float s = 0.0f;
#pragma unroll 8
        for (int cc = 0; cc < 64; cc++)
            s += tanhf(rp[cc] + w1p[cc]) * w2p[cc];
        s += __shfl_down_sync(0xffffffffu, s, 2, 4);
        s += __shfl_down_sync(0xffffffffu, s, 1, 4);
        if (q == 0) g_att[r0 + chunk * 64 + row] = s + ba2v;
        __syncthreads();
    }
}

// ------------------------- bf16 GEMM body (projection) ------------------------
#define SA_STRIDE 40
#define SB_STRIDE 264
#define SA_ELEMS (128 * SA_STRIDE)
#define SB_ELEMS (32 * SB_STRIDE)
#define GEMM_SMEM ((2 * SA_ELEMS + 2 * SB_ELEMS) * 2)

__device__ __forceinline__ void gemm_body(const bf16* __restrict__ A,
                                          const bf16* __restrict__ Bw,
                                          float* __restrict__ C, int r0,
                                          bf16* smem) {
    const int tid  = threadIdx.x;
    const int warp = tid >> 5;
    const int wr   = warp >> 2;
    const int wc   = warp & 3;
    bf16* sA[2] = { smem, smem + SA_ELEMS };
    bf16* sB[2] = { smem + 2 * SA_ELEMS, smem + 2 * SA_ELEMS + SB_ELEMS };

    wmma::fragment<wmma::accumulator, 16, 16, 16, float> c[4][4];
#pragma unroll
    for (int i = 0; i < 4; i++)
#pragma unroll
        for (int j = 0; j < 4; j++) wmma::fill_fragment(c[i][j], 0.0f);

    auto load_tile = [&](int it, int s) {
        int kk = it * 32;
#pragma unroll
        for (int c0 = 0; c0 < 2; c0++) {
            int ch = tid + c0 * 256;
            int row = ch >> 2, q = ch & 3;
            cp16(sA[s] + row * SA_STRIDE + q * 8,
                 A + (long)(r0 + row) * ND + kk + q * 8);
        }
#pragma unroll
        for (int c0 = 0; c0 < 4; c0++) {
            int ch = tid + c0 * 256;
            int row = ch >> 5, q = ch & 31;
            cp16(sB[s] + row * SB_STRIDE + q * 8,
                 Bw + (long)(kk + row) * NH + q * 8);
        }
        asm volatile("cp.async.commit_group;");
    };

    load_tile(0, 0);
    for (int it = 0; it < ND / 32; it++) {
        int s = it & 1;
        if (it + 1 < ND / 32) {
            load_tile(it + 1, s ^ 1);
            asm volatile("cp.async.wait_group 1;");
        } else {
            asm volatile("cp.async.wait_group 0;");
        }
        __syncthreads();
#pragma unroll
        for (int ks = 0; ks < 32; ks += 16) {
            wmma::fragment<wmma::matrix_a, 16, 16, 16, bf16, wmma::row_major> af[4];
            wmma::fragment<wmma::matrix_b, 16, 16, 16, bf16, wmma::row_major> bfr[4];
#pragma unroll
            for (int i = 0; i < 4; i++)
                wmma::load_matrix_sync(af[i], sA[s] + (wr * 64 + i * 16) * SA_STRIDE + ks, SA_STRIDE);
#pragma unroll
            for (int j = 0; j < 4; j++)
                wmma::load_matrix_sync(bfr[j], sB[s] + ks * SB_STRIDE + wc * 64 + j * 16, SB_STRIDE);
#pragma unroll
            for (int i = 0; i < 4; i++)
#pragma unroll
                for (int j = 0; j < 4; j++)
                    wmma::mma_sync(c[i][j], af[i], bfr[j], c[i][j]);
        }
        __syncthreads();
    }
#pragma unroll
    for (int i = 0; i < 4; i++)
#pragma unroll
        for (int j = 0; j < 4; j++)
            wmma::store_matrix_sync(&C[(long)(r0 + wr * 64 + i * 16) * NH + wc * 64 + j * 16],
                                    c[i][j], NH, wmma::mem_row_major);
}

__global__ __launch_bounds__(256, 1) void k_gemm_proj() {
    extern __shared__ bf16 smemp[];
    int seg = blockIdx.y;
    const bf16* A = (seg == 0) ? g_aggb[0] : (seg == 1) ? g_aggb[1]
                  : (seg == 2) ? g_diffb : g_encb;
    const bf16* B = (seg < 2) ? g_W1b : (seg == 2) ? g_Wdb : g_Wrb;
    gemm_body(A, B, g_h1[seg], blockIdx.x * 128, smemp);
}

// ------------------------- softmax + weight normalize ------------------------
__global__ void k_softmax(const float* __restrict__ nw, const float* __restrict__ nw2) {
    int t = blockIdx.x * blockDim.x + threadIdx.x;
    if (t >= 2 * NB) return;
    int g = t >> 10, b = t & 1023;
    const float* nwp = (g ? nw2 : nw) + b * NK;
    const float* a = g_att + g * NR + b * NK;
    float m = -1e30f;
#pragma unroll
    for (int k = 0; k < NK; k++) m = fmaxf(m, a[k]);
    float e[NK], s = 0.0f;
#pragma unroll
    for (int k = 0; k < NK; k++) { e[k] = __expf(a[k] - m); s += e[k]; }
    float inv_s = 1.0f / s;
    float w[NK], ws = 0.0f;
#pragma unroll
    for (int k = 0; k < NK; k++) { w[k] = nwp[k] * e[k] * inv_s; ws += w[k]; }
    float inv = 1.0f / (ws + 1e-12f);
    float tot = 0.0f;
#pragma unroll
    for (int k = 0; k < NK; k++) { float v = w[k] * inv; g_w[t * NK + k] = v; tot += v; }
    g_wsum[t] = tot;
}

// ------------------------- weighted aggregation (reads nfb) ------------------
__global__ __launch_bounds__(256) void k_agg(const float* __restrict__ enc) {
    int cta = blockIdx.x;
    int g = cta >> 10, b = cta & 1023;
    __shared__ float ws[NK];
    __shared__ float s_wsum;
    if (threadIdx.x < NK) ws[threadIdx.x] = g_w[cta * NK + threadIdx.x];
    if (threadIdx.x == 0) s_wsum = g_wsum[cta];
    __syncthreads();
    const bf16* base = g_nfb + (long)(g * NR + b * NK) * ND;
    for (int p = threadIdx.x; p < 500; p += 256) {
        float acc[8] = {0, 0, 0, 0, 0, 0, 0, 0};
#pragma unroll
        for (int k = 0; k < NK; k++) {
            int4 v = *(const int4*)(base + (long)k * ND + p * 8);
            const __nv_bfloat162* h = (const __nv_bfloat162*)&v;
            float wk = ws[k];
#pragma unroll
            for (int q = 0; q < 4; q++) {
                float2 f = __bfloat1622float2(h[q]);
                acc[2 * q]     += wk * f.x;
                acc[2 * q + 1] += wk * f.y;
            }
        }
        bf16 oa[8];
#pragma unroll
        for (int q = 0; q < 8; q++) oa[q] = __float2bfloat16(acc[q]);
        *(int4*)(g_aggb[g] + (long)b * ND + p * 8) = *(int4*)oa;
        if (g == 0) {
            float4 e0 = *(const float4*)(enc + (long)b * ND + p * 8);
            float4 e1 = *(const float4*)(enc + (long)b * ND + p * 8 + 4);
            float ev[8] = { e0.x, e0.y, e0.z, e0.w, e1.x, e1.y, e1.z, e1.w };
            bf16 od[8];
#pragma unroll
            for (int q = 0; q < 8; q++) od[q] = __float2bfloat16(acc[q] - s_wsum * ev[q]);
            *(int4*)(g_diffb + (long)b * ND + p * 8) = *(int4*)od;
        }
    }
}

// ------------------------- final: layer2, gates, LN, output ------------------
__global__ __launch_bounds__(256) void k_final(
    const float* __restrict__ W2, const float* __restrict__ b1, const float* __restrict__ b2,
    const float* __restrict__ bd, const float* __restrict__ br,
    const float* __restrict__ gamma, const float* __restrict__ beta,
    const float* __restrict__ mg, const float* __restrict__ cgg,
    float* __restrict__ out)
{
    int b = blockIdx.x, n = threadIdx.x;
    __shared__ float h1a[NH], h1b[NH];
    h1a[n] = fmaxf(g_h1[0][b * NH + n] + b1[n], 0.0f);
    h1b[n] = fmaxf(g_h1[1][b * NH + n] + b1[n], 0.0f);
    __syncthreads();
    float aa = b2[n], ab = b2[n];
#pragma unroll 8
    for (int m = 0; m < NH; m++) {
        float w = W2[m * NH + n];
        aa += h1a[m] * w;
        ab += h1b[m] * w;
    }
    float h2a = fmaxf(aa, 0.0f), h2b = fmaxf(ab, 0.0f);
    float gcg = 1.0f / (1.0f + __expf(-cgg[n]));
    float p = gcg * h2a + (1.0f - gcg) * h2b;
    p += fmaxf(g_h1[2][b * NH + n] + bd[n], 0.0f);
    p += fmaxf(g_h1[3][b * NH + n] + br[n], 0.0f);
    __shared__ float red[16];
    float s1 = p, s2 = p * p;
#pragma unroll
    for (int o = 16; o; o >>= 1) {
        s1 += __shfl_down_sync(0xffffffffu, s1, o);
        s2 += __shfl_down_sync(0xffffffffu, s2, o);
    }
    int lane = n & 31, wid = n >> 5;
    if (lane == 0) { red[wid] = s1; red[8 + wid] = s2; }
    __syncthreads();
    if (n == 0) {
        float t1 = 0.f, t2 = 0.f;
        for (int i = 0; i < 8; i++) { t1 += red[i]; t2 += red[8 + i]; }
        red[0] = t1; red[8] = t2;
    }
    __syncthreads();
    float mu = red[0] * (1.0f / NH);
    float var = red[8] * (1.0f / NH) - mu * mu;
    float y = (p - mu) * rsqrtf(var + 1e-5f) * gamma[n] + beta[n];
    float mgs = 1.0f / (1.0f + __expf(-mg[n]));
    out[(long)b * OUTW + ND + n] = mgs * y;
}

// ------------------------- launch ---------------------------------------------
extern "C" void kernel_launch(void* const* d_in, const int* in_sizes, int n_in,
                              void* d_out, int out_size) {
    const float* enc = (const float*)d_in[0];
    const int*   ni  = (const int*)d_in[1];
    const float* nw  = (const float*)d_in[2];
    const int*   ni2 = (const int*)d_in[3];
    const float* nw2 = (const float*)d_in[4];
    const float* sp  = (const float*)d_in[5];
    const float* un  = (const float*)d_in[6];
    const float* W1  = (const float*)d_in[7];
    const float* b1  = (const float*)d_in[8];
    const float* W2  = (const float*)d_in[9];
    const float* b2  = (const float*)d_in[10];
    const float* Wa1 = (const float*)d_in[11];
    const float* ba1 = (const float*)d_in[12];
    const float* Wa2 = (const float*)d_in[13];
    const float* ba2 = (const float*)d_in[14];
    const float* Wd  = (const float*)d_in[15];
    const float* bd  = (const float*)d_in[16];
    const float* Wr  = (const float*)d_in[17];
    const float* br  = (const float*)d_in[18];
    const float* gamma = (const float*)d_in[19];
    const float* beta  = (const float*)d_in[20];
    const float* mg    = (const float*)d_in[21];
    const float* cgg   = (const float*)d_in[22];
    float* out = (float*)d_out;

    cudaFuncSetAttribute(k_gatt,      cudaFuncAttributeMaxDynamicSharedMemorySize, GT_SMEM);
    cudaFuncSetAttribute(k_gemm_proj, cudaFuncAttributeMaxDynamicSharedMemorySize, GEMM_SMEM);

    k_prep<<<4128, 256>>>(ni, ni2, Wa1, W1, Wd, Wr, enc, out);
    k_gatt<<<NRT / 128, 256, GT_SMEM>>>(sp, un, ba1, Wa2, ba2);
    k_softmax<<<8, 256>>>(nw, nw2);
    k_agg<<<2 * NB, 256>>>(enc);
    k_gemm_proj<<<dim3(NB / 128, 4), 256, GEMM_SMEM>>>();
    k_final<<<NB, 256>>>(W2, b1, b2, bd, br, gamma, beta, mg, cgg, out);
}